// round 4
// baseline (speedup 1.0000x reference)
#include <cuda_runtime.h>
#include <cuda_bf16.h>
#include <math.h>

// Problem constants
#define VOCAB 32000
#define DMODEL 512
#define NH 8
#define NL 6
#define SEQ 1024
#define BATCH 4
#define DH 64
#define WIN 102
#define NTOK (BATCH*SEQ)          // 4096
#define NELEM (NTOK*DMODEL)       // 2097152

// ---------------- scratch (device globals; no allocation allowed) ----------
__device__ float g_x[NELEM];
__device__ float g_q[NELEM];
__device__ float g_k[NELEM];
__device__ float g_v[NELEM];
__device__ float g_att[NELEM];
__device__ float g_proj[NELEM];
__device__ float g_u[NTOK*NH];
__device__ float g_pooled[BATCH*DMODEL];

// ---------------- embedding -------------------------------------------------
__global__ void embed_kernel(const int* __restrict__ ids,
                             const float* __restrict__ tok,
                             const float* __restrict__ pos,
                             float* __restrict__ x)
{
    int idx = blockIdx.x * blockDim.x + threadIdx.x;   // < NELEM
    int d = idx & (DMODEL-1);
    int t = idx >> 9;          // token index b*SEQ+s
    int s = t & (SEQ-1);
    x[idx] = tok[ids[t]*DMODEL + d] + pos[s*DMODEL + d];
}

// ---------------- SGEMM C[M,N] = A[M,K] @ B[K,N] + bias[N] -----------------
// BM=128, BN=128, BK=8, TM=TN=8, 256 threads.
#define BM 128
#define BN 128
#define BKK 8
#define TM 8
#define TN 8

__global__ __launch_bounds__(256)
void sgemm_bias(const float* __restrict__ A, const float* __restrict__ B,
                const float* __restrict__ bias, float* __restrict__ C,
                int M, int N, int K)
{
    __shared__ __align__(16) float As[BKK][BM];
    __shared__ __align__(16) float Bs[BKK][BN];

    int tid = threadIdx.x;
    int tr = tid >> 4;          // 0..15
    int tc = tid & 15;          // 0..15
    int rowBase = blockIdx.y * BM;
    int colBase = blockIdx.x * BN;

    int aRow = tid >> 1;        // 0..127
    int aCol = (tid & 1) * 4;   // 0 or 4
    int bRow = tid >> 5;        // 0..7
    int bCol = (tid & 31) * 4;  // 0..124

    float acc[TM][TN];
#pragma unroll
    for (int i = 0; i < TM; i++)
#pragma unroll
        for (int j = 0; j < TN; j++) acc[i][j] = 0.f;

    const float* Aptr = A + rowBase * K;
    const float* Bptr = B + colBase;

    for (int k0 = 0; k0 < K; k0 += BKK) {
        float4 av = *(const float4*)(Aptr + aRow * K + k0 + aCol);
        As[aCol+0][aRow] = av.x;
        As[aCol+1][aRow] = av.y;
        As[aCol+2][aRow] = av.z;
        As[aCol+3][aRow] = av.w;
        float4 bv = *(const float4*)(Bptr + (k0 + bRow) * N + bCol);
        *(float4*)&Bs[bRow][bCol] = bv;
        __syncthreads();
#pragma unroll
        for (int kk = 0; kk < BKK; kk++) {
            float4 a0 = *(const float4*)&As[kk][tr*TM];
            float4 a1 = *(const float4*)&As[kk][tr*TM+4];
            float4 b0 = *(const float4*)&Bs[kk][tc*TN];
            float4 b1 = *(const float4*)&Bs[kk][tc*TN+4];
            float ra[TM] = {a0.x,a0.y,a0.z,a0.w,a1.x,a1.y,a1.z,a1.w};
            float rb[TN] = {b0.x,b0.y,b0.z,b0.w,b1.x,b1.y,b1.z,b1.w};
#pragma unroll
            for (int i = 0; i < TM; i++)
#pragma unroll
                for (int j = 0; j < TN; j++)
                    acc[i][j] += ra[i] * rb[j];
        }
        __syncthreads();
    }

#pragma unroll
    for (int i = 0; i < TM; i++) {
        int r = rowBase + tr*TM + i;
#pragma unroll
        for (int j = 0; j < TN; j++) {
            int c = colBase + tc*TN + j;
            C[r*N + c] = acc[i][j] + bias[c];
        }
    }
}

// ---------------- gate u = sigmoid(x @ Wu + bu) ----------------------------
__global__ void gate_kernel(const float* __restrict__ x,
                            const float* __restrict__ Wu,
                            const float* __restrict__ bu,
                            float* __restrict__ u)
{
    int token = blockIdx.x;            // 0..NTOK-1
    int h = threadIdx.x >> 5;          // warp = head
    int lane = threadIdx.x & 31;
    const float* xp = x + token * DMODEL;
    float s = 0.f;
#pragma unroll 4
    for (int d = lane; d < DMODEL; d += 32)
        s += xp[d] * Wu[d * NH + h];
    for (int o = 16; o; o >>= 1) s += __shfl_xor_sync(0xffffffffu, s, o);
    if (lane == 0)
        u[token * NH + h] = 1.f / (1.f + __expf(-(s + bu[h])));
}

// ---------------- banded attention, one warp per (b,h,i), gated output -----
__global__ void attn_kernel(const float* __restrict__ q,
                            const float* __restrict__ k,
                            const float* __restrict__ v,
                            const float* __restrict__ u,
                            float* __restrict__ out)
{
    int warp = (blockIdx.x * blockDim.x + threadIdx.x) >> 5;
    int lane = threadIdx.x & 31;
    int i = warp & (SEQ-1);
    int bh = warp >> 10;
    int h = bh & (NH-1);
    int b = bh >> 3;

    const float* qp = q + (b*SEQ + i)*DMODEL + h*DH;
    float q0 = qp[lane*2], q1 = qp[lane*2+1];

    int jlo = i - WIN; if (jlo < 0) jlo = 0;
    int jhi = i + WIN; if (jhi > SEQ-1) jhi = SEQ-1;

    const float* kb = k + b*SEQ*DMODEL + h*DH;
    const float* vb = v + b*SEQ*DMODEL + h*DH;

    float m = -1e30f, l = 0.f, a0 = 0.f, a1 = 0.f;
    for (int j = jlo; j <= jhi; j++) {
        const float* kp = kb + j*DMODEL;
        float s = q0*kp[lane*2] + q1*kp[lane*2+1];
        for (int o = 16; o; o >>= 1) s += __shfl_xor_sync(0xffffffffu, s, o);
        s *= 0.125f;   // 1/sqrt(64)
        float nm = fmaxf(m, s);
        float c = __expf(m - nm);
        float p = __expf(s - nm);
        const float* vp = vb + j*DMODEL;
        a0 = a0*c + p*vp[lane*2];
        a1 = a1*c + p*vp[lane*2+1];
        l = l*c + p;
        m = nm;
    }
    float gscale = u[(b*SEQ + i)*NH + h] / l;
    float* op = out + (b*SEQ + i)*DMODEL + h*DH;
    op[lane*2]   = a0 * gscale;
    op[lane*2+1] = a1 * gscale;
}

// ---------------- (residual add) + layernorm -------------------------------
__device__ __forceinline__ float warpsum(float v) {
    for (int o = 16; o; o >>= 1) v += __shfl_xor_sync(0xffffffffu, v, o);
    return v;
}

__global__ void add_ln_kernel(const float* __restrict__ x,
                              const float* __restrict__ r,
                              const float* __restrict__ g,
                              const float* __restrict__ bb,
                              float* __restrict__ out,
                              int has_res)
{
    int token = blockIdx.x;
    int tid = threadIdx.x;   // 128 threads
    const float* xp = x + token * DMODEL;
    const float* rp = r + token * DMODEL;

    float v[4];
    float s = 0.f, sq = 0.f;
#pragma unroll
    for (int c = 0; c < 4; c++) {
        int d = tid + c*128;
        float t = xp[d] + (has_res ? rp[d] : 0.f);
        v[c] = t; s += t; sq += t*t;
    }
    s = warpsum(s); sq = warpsum(sq);
    __shared__ float ss[4], ssq[4];
    int w = tid >> 5;
    if ((tid & 31) == 0) { ss[w] = s; ssq[w] = sq; }
    __syncthreads();
    float tot = ss[0]+ss[1]+ss[2]+ss[3];
    float totq = ssq[0]+ssq[1]+ssq[2]+ssq[3];
    float mu = tot * (1.f/DMODEL);
    float var = totq * (1.f/DMODEL) - mu*mu;
    float rstd = rsqrtf(var + 1e-5f);
#pragma unroll
    for (int c = 0; c < 4; c++) {
        int d = tid + c*128;
        out[token*DMODEL + d] = (v[c]-mu)*rstd*g[d] + bb[d];
    }
}

// ---------------- masked mean pool -----------------------------------------
__global__ void pool_kernel(const float* __restrict__ y,
                            const float* __restrict__ mask,
                            float* __restrict__ pooled)
{
    int b = blockIdx.x;
    int d = threadIdx.x;    // 512 threads
    float s = 0.f;
    for (int ss = 0; ss < SEQ; ss++)
        s += y[((b<<10) + ss)*DMODEL + d] * mask[(b<<10) + ss];
    pooled[b*DMODEL + d] = s * (1.f/SEQ);
}

// ---------------- classifier: logits[b,v] = pooled[b,:]·W[:,v] + cb[v] -----
__global__ __launch_bounds__(256)
void cls_kernel(const float* __restrict__ pooled,
                const float* __restrict__ W,
                const float* __restrict__ cb,
                float* __restrict__ logits)
{
    __shared__ float sp[BATCH*DMODEL];
    int tid = threadIdx.x;
    for (int i = tid; i < BATCH*DMODEL; i += 256) sp[i] = pooled[i];
    __syncthreads();
    int vcol = blockIdx.x*256 + tid;
    float a0=0.f, a1=0.f, a2=0.f, a3=0.f;
#pragma unroll 4
    for (int d = 0; d < DMODEL; d++) {
        float w = W[d*VOCAB + vcol];
        a0 += sp[d]*w;
        a1 += sp[DMODEL+d]*w;
        a2 += sp[2*DMODEL+d]*w;
        a3 += sp[3*DMODEL+d]*w;
    }
    float c = cb[vcol];
    logits[vcol]           = a0 + c;
    logits[VOCAB + vcol]   = a1 + c;
    logits[2*VOCAB + vcol] = a2 + c;
    logits[3*VOCAB + vcol] = a3 + c;
}

// ---------------- launch ----------------------------------------------------
extern "C" void kernel_launch(void* const* d_in, const int* in_sizes, int n_in,
                              void* d_out, int out_size)
{
    const int*   input_ids = (const int*)  d_in[0];
    const float* attn_mask = (const float*)d_in[1];
    const float* tok_emb   = (const float*)d_in[2];
    const float* pos_emb   = (const float*)d_in[3];
    const float* Wq        = (const float*)d_in[4];
    const float* Wk        = (const float*)d_in[5];
    const float* Wv        = (const float*)d_in[6];
    const float* Wo        = (const float*)d_in[7];
    const float* bq        = (const float*)d_in[8];
    const float* bk        = (const float*)d_in[9];
    const float* bv        = (const float*)d_in[10];
    const float* bo        = (const float*)d_in[11];
    const float* Wu        = (const float*)d_in[12];
    const float* bu        = (const float*)d_in[13];
    const float* ln_g      = (const float*)d_in[14];
    const float* ln_b      = (const float*)d_in[15];
    const float* norm_g    = (const float*)d_in[16];
    const float* norm_b    = (const float*)d_in[17];
    const float* cls_W     = (const float*)d_in[18];
    const float* cls_b     = (const float*)d_in[19];
    float* logits = (float*)d_out;

    float *x, *q, *k, *v, *att, *proj, *u, *pooled;
    cudaGetSymbolAddress((void**)&x,      g_x);
    cudaGetSymbolAddress((void**)&q,      g_q);
    cudaGetSymbolAddress((void**)&k,      g_k);
    cudaGetSymbolAddress((void**)&v,      g_v);
    cudaGetSymbolAddress((void**)&att,    g_att);
    cudaGetSymbolAddress((void**)&proj,   g_proj);
    cudaGetSymbolAddress((void**)&u,      g_u);
    cudaGetSymbolAddress((void**)&pooled, g_pooled);

    // embedding
    embed_kernel<<<NELEM/256, 256>>>(input_ids, tok_emb, pos_emb, x);

    dim3 ggrid(DMODEL/BN, NTOK/BM);   // (4, 32)
    for (int l = 0; l < NL; l++) {
        const float* wq = Wq + l*DMODEL*DMODEL;
        const float* wk = Wk + l*DMODEL*DMODEL;
        const float* wv = Wv + l*DMODEL*DMODEL;
        const float* wo = Wo + l*DMODEL*DMODEL;

        sgemm_bias<<<ggrid, 256>>>(x, wq, bq + l*DMODEL, q, NTOK, DMODEL, DMODEL);
        sgemm_bias<<<ggrid, 256>>>(x, wk, bk + l*DMODEL, k, NTOK, DMODEL, DMODEL);
        sgemm_bias<<<ggrid, 256>>>(x, wv, bv + l*DMODEL, v, NTOK, DMODEL, DMODEL);

        gate_kernel<<<NTOK, NH*32>>>(x, Wu + l*DMODEL*NH, bu + l*NH, u);

        // one warp per (b,h,i): 32768 warps -> 4096 blocks of 256 threads
        attn_kernel<<<(BATCH*NH*SEQ*32)/256, 256>>>(q, k, v, u, att);

        sgemm_bias<<<ggrid, 256>>>(att, wo, bo + l*DMODEL, proj, NTOK, DMODEL, DMODEL);

        add_ln_kernel<<<NTOK, 128>>>(x, proj, ln_g + l*DMODEL, ln_b + l*DMODEL, x, 1);
    }

    // final LN into q (reuse), pool, classify
    add_ln_kernel<<<NTOK, 128>>>(x, x, norm_g, norm_b, q, 0);
    pool_kernel<<<BATCH, DMODEL>>>(q, attn_mask, pooled);
    cls_kernel<<<VOCAB/256, 256>>>(pooled, cls_W, cls_b, logits);
}